// round 4
// baseline (speedup 1.0000x reference)
#include <cuda_runtime.h>
#include <stdint.h>

#define BATCH 4096
#define IN_F  2048
#define OUT_F 4096
#define WORDS (IN_F / 64)     // 32 u64 per row
#define HT_SIZE 16384         // power of 2, 4x oversized

// Scratch (allocation-free: __device__ globals)
__device__ uint64_t g_xbits[(size_t)BATCH * WORDS];
__device__ uint64_t g_pbits[(size_t)OUT_F * WORDS];
__device__ uint64_t g_xsig[BATCH];
__device__ uint64_t g_psig[OUT_F];
__device__ uint32_t g_ht[HT_SIZE];       // 0 = empty, else o+1

__device__ __forceinline__ uint32_t hash_sig(uint64_t s)
{
    s ^= s >> 33; s *= 0xff51afd7ed558ccdULL; s ^= s >> 33;
    return (uint32_t)s & (HT_SIZE - 1);
}

// -----------------------------------------------------------------------------
// Kernel 1: fused pack + zero-fill.
//   * 1024 blocks x 256 threads. Each block packs 8 rows (one warp per row)
//     AND zero-fills a 4096-float4 slice of the output.
//   * Pack: float4 loads, 4 ballots/iter. Bit order within packed words is a
//     fixed permutation of element order, identical for x and path rows, so
//     packed-row equality <=> original-bit-row equality (exact).
// -----------------------------------------------------------------------------
__global__ __launch_bounds__(256) void fsu_pack_zero_kernel(
    const float* __restrict__ x,
    const float* __restrict__ w,
    const float* __restrict__ rng,
    float4* __restrict__ outv)
{
    // ---- zero-fill slice (independent of pack; pure store stream) ----
    {
        const float4 z = make_float4(0.0f, 0.0f, 0.0f, 0.0f);
        const int base = blockIdx.x * 4096;          // 4M float4 / 1024 blocks
        #pragma unroll
        for (int k = 0; k < 16; ++k)
            outv[base + k * 256 + threadIdx.x] = z;
    }

    // ---- pack 8 rows (one warp per row) ----
    const int gwarp = (blockIdx.x * blockDim.x + threadIdx.x) >> 5;
    const int lane  = threadIdx.x & 31;
    const bool isX  = gwarp < BATCH;
    const int row   = isX ? gwarp : (gwarp - BATCH);

    const float rv = __ldg(rng);
    const float4* src = reinterpret_cast<const float4*>(
        (isX ? (x + (size_t)row * IN_F) : (w + (size_t)row * IN_F)));

    uint64_t sig = 0;
    uint64_t myword = 0;

    #pragma unroll
    for (int it = 0; it < IN_F / 128; ++it) {        // 16 iterations
        const float4 v = __ldg(src + it * 32 + lane);
        bool b0, b1, b2, b3;
        if (isX) {
            b0 = (v.x > 0.5f); b1 = (v.y > 0.5f);
            b2 = (v.z > 0.5f); b3 = (v.w > 0.5f);
        } else {
            // BinGen/BSGen: prob=(w+1)*0.5; source=round(prob*256); bit = source > rng
            b0 = (rintf((v.x + 1.0f) * 0.5f * 256.0f) > rv);
            b1 = (rintf((v.y + 1.0f) * 0.5f * 256.0f) > rv);
            b2 = (rintf((v.z + 1.0f) * 0.5f * 256.0f) > rv);
            b3 = (rintf((v.w + 1.0f) * 0.5f * 256.0f) > rv);
        }
        const uint32_t m0 = __ballot_sync(0xFFFFFFFFu, b0);
        const uint32_t m1 = __ballot_sync(0xFFFFFFFFu, b1);
        const uint32_t m2 = __ballot_sync(0xFFFFFFFFu, b2);
        const uint32_t m3 = __ballot_sync(0xFFFFFFFFu, b3);
        const uint64_t wa = (uint64_t)m0 | ((uint64_t)m1 << 32);
        const uint64_t wb = (uint64_t)m2 | ((uint64_t)m3 << 32);
        if (lane == 2 * it)     myword = wa;
        if (lane == 2 * it + 1) myword = wb;
        sig = sig * 0x9E3779B97F4A7C15ull + wa;
        sig = sig * 0x9E3779B97F4A7C15ull + wb;
    }

    if (isX) {
        g_xbits[(size_t)row * WORDS + lane] = myword;
        if (lane == 0) g_xsig[row] = sig;
    } else {
        g_pbits[(size_t)row * WORDS + lane] = myword;
        if (lane == 0) g_psig[row] = sig;
    }
}

// Exact verification: full 2048-bit compare (equal sigs is necessary but we
// never trust it alone — collisions cannot produce wrong output).
__device__ bool fsu_full_cmp(int b, int o)
{
    const uint64_t* xb = &g_xbits[(size_t)b * WORDS];
    const uint64_t* pb = &g_pbits[(size_t)o * WORDS];
    #pragma unroll 8
    for (int k = 0; k < WORDS; ++k)
        if (__ldg(xb + k) != __ldg(pb + k)) return false;
    return true;
}

// -----------------------------------------------------------------------------
// Kernel 2: single block does reset -> insert -> probe -> direct match writes.
// Runs after kernel 1 on the stream, so out[] is already zeroed.
// -----------------------------------------------------------------------------
__global__ __launch_bounds__(1024) void fsu_match_kernel(float* __restrict__ out)
{
    const int tid = threadIdx.x;

    // reset hash table
    #pragma unroll
    for (int i = tid; i < HT_SIZE; i += 1024)
        g_ht[i] = 0;
    __syncthreads();

    // insert all psigs (stores o+1)
    #pragma unroll
    for (int o = tid; o < OUT_F; o += 1024) {
        uint32_t h = hash_sig(g_psig[o]);
        while (atomicCAS(&g_ht[h], 0u, (uint32_t)(o + 1)) != 0u)
            h = (h + 1) & (HT_SIZE - 1);
    }
    __syncthreads();

    // probe each batch row; verified matches written directly (out pre-zeroed)
    #pragma unroll
    for (int b = tid; b < BATCH; b += 1024) {
        const uint64_t xs = g_xsig[b];
        uint32_t h = hash_sig(xs);
        uint32_t e;
        while ((e = g_ht[h]) != 0u) {
            const int o = (int)e - 1;
            if (g_psig[o] == xs && fsu_full_cmp(b, o))
                out[(size_t)b * OUT_F + o] = 1.0f;
            h = (h + 1) & (HT_SIZE - 1);
        }
    }
}

extern "C" void kernel_launch(void* const* d_in, const int* in_sizes, int n_in,
                              void* d_out, int out_size)
{
    const float* x   = (const float*)d_in[0];
    const float* w   = (const float*)d_in[1];
    const float* rng = (const float*)d_in[2];
    float* out = (float*)d_out;

    // (BATCH + OUT_F) warps = 8192 -> 1024 blocks of 8 warps; each block also
    // zero-fills 4096 float4 of the output.
    fsu_pack_zero_kernel<<<1024, 256>>>(x, w, rng,
                                        reinterpret_cast<float4*>(out));

    fsu_match_kernel<<<1, 1024>>>(out);
}

// round 5
// speedup vs baseline: 1.0960x; 1.0960x over previous
#include <cuda_runtime.h>
#include <stdint.h>

#define BATCH 4096
#define IN_F  2048
#define OUT_F 4096
#define WORDS (IN_F / 64)     // 32 u64 per row
#define HT_SIZE 8192          // power of 2; 4096 entries -> 50% load, 32 KB smem

// Scratch (allocation-free: __device__ globals)
__device__ uint64_t g_xbits[(size_t)BATCH * WORDS];
__device__ uint64_t g_pbits[(size_t)OUT_F * WORDS];
__device__ uint64_t g_xsig[BATCH];
__device__ uint64_t g_psig[OUT_F];

__device__ __forceinline__ uint32_t hash_sig(uint64_t s)
{
    s ^= s >> 33; s *= 0xff51afd7ed558ccdULL; s ^= s >> 33;
    return (uint32_t)s & (HT_SIZE - 1);
}

// -----------------------------------------------------------------------------
// Kernel 1: fused pack + zero-fill (HBM-bound: 64 MB read + 64 MB write).
//   * 1024 blocks x 256 threads. Each block packs 8 rows (one warp per row)
//     AND zero-fills a 4096-float4 slice of the output.
//   * Pack: float4 loads, 4 ballots/iter. Bit order within packed words is a
//     fixed permutation of element order, identical for x and path rows, so
//     packed-row equality <=> original-bit-row equality (exact).
// -----------------------------------------------------------------------------
__global__ __launch_bounds__(256) void fsu_pack_zero_kernel(
    const float* __restrict__ x,
    const float* __restrict__ w,
    const float* __restrict__ rng,
    float4* __restrict__ outv)
{
    // ---- zero-fill slice (pure store stream, overlaps with pack loads) ----
    {
        const float4 z = make_float4(0.0f, 0.0f, 0.0f, 0.0f);
        const int base = blockIdx.x * 4096;          // 4M float4 / 1024 blocks
        #pragma unroll
        for (int k = 0; k < 16; ++k)
            outv[base + k * 256 + threadIdx.x] = z;
    }

    // ---- pack 8 rows (one warp per row) ----
    const int gwarp = (blockIdx.x * blockDim.x + threadIdx.x) >> 5;
    const int lane  = threadIdx.x & 31;
    const bool isX  = gwarp < BATCH;
    const int row   = isX ? gwarp : (gwarp - BATCH);

    const float rv = __ldg(rng);
    const float4* src = reinterpret_cast<const float4*>(
        (isX ? (x + (size_t)row * IN_F) : (w + (size_t)row * IN_F)));

    uint64_t sig = 0;
    uint64_t myword = 0;

    #pragma unroll
    for (int it = 0; it < IN_F / 128; ++it) {        // 16 iterations
        const float4 v = __ldg(src + it * 32 + lane);
        bool b0, b1, b2, b3;
        if (isX) {
            b0 = (v.x > 0.5f); b1 = (v.y > 0.5f);
            b2 = (v.z > 0.5f); b3 = (v.w > 0.5f);
        } else {
            // BinGen/BSGen: prob=(w+1)*0.5; source=round(prob*256); bit = source > rng
            b0 = (rintf((v.x + 1.0f) * 0.5f * 256.0f) > rv);
            b1 = (rintf((v.y + 1.0f) * 0.5f * 256.0f) > rv);
            b2 = (rintf((v.z + 1.0f) * 0.5f * 256.0f) > rv);
            b3 = (rintf((v.w + 1.0f) * 0.5f * 256.0f) > rv);
        }
        const uint32_t m0 = __ballot_sync(0xFFFFFFFFu, b0);
        const uint32_t m1 = __ballot_sync(0xFFFFFFFFu, b1);
        const uint32_t m2 = __ballot_sync(0xFFFFFFFFu, b2);
        const uint32_t m3 = __ballot_sync(0xFFFFFFFFu, b3);
        const uint64_t wa = (uint64_t)m0 | ((uint64_t)m1 << 32);
        const uint64_t wb = (uint64_t)m2 | ((uint64_t)m3 << 32);
        if (lane == 2 * it)     myword = wa;
        if (lane == 2 * it + 1) myword = wb;
        sig = sig * 0x9E3779B97F4A7C15ull + wa;
        sig = sig * 0x9E3779B97F4A7C15ull + wb;
    }

    if (isX) {
        g_xbits[(size_t)row * WORDS + lane] = myword;
        if (lane == 0) g_xsig[row] = sig;
    } else {
        g_pbits[(size_t)row * WORDS + lane] = myword;
        if (lane == 0) g_psig[row] = sig;
    }
}

// Exact verification: full 2048-bit compare. Equal sigs alone is never
// trusted — collisions cannot produce wrong output.
__device__ bool fsu_full_cmp(int b, int o)
{
    const uint64_t* xb = &g_xbits[(size_t)b * WORDS];
    const uint64_t* pb = &g_pbits[(size_t)o * WORDS];
    #pragma unroll 8
    for (int k = 0; k < WORDS; ++k)
        if (__ldg(xb + k) != __ldg(pb + k)) return false;
    return true;
}

// -----------------------------------------------------------------------------
// Kernel 2: 4 blocks x 1024 threads. Each block builds the full psig hash
// table in SHARED memory (smem CAS, smem probes — no global round trips in
// the dependent chain), then each thread probes exactly one batch row.
// Runs after kernel 1 on the stream, so out[] is already zeroed.
// -----------------------------------------------------------------------------
__global__ __launch_bounds__(1024) void fsu_match_kernel(float* __restrict__ out)
{
    __shared__ uint32_t s_ht[HT_SIZE];               // 32 KB
    const int tid = threadIdx.x;

    #pragma unroll
    for (int i = tid; i < HT_SIZE; i += 1024)
        s_ht[i] = 0;
    __syncthreads();

    // insert all psigs (stores o+1); coalesced global reads, smem CAS
    #pragma unroll
    for (int o = tid; o < OUT_F; o += 1024) {
        uint32_t h = hash_sig(__ldg(&g_psig[o]));
        while (atomicCAS(&s_ht[h], 0u, (uint32_t)(o + 1)) != 0u)
            h = (h + 1) & (HT_SIZE - 1);
    }
    __syncthreads();

    // probe: one batch row per thread
    const int b = blockIdx.x * 1024 + tid;
    const uint64_t xs = __ldg(&g_xsig[b]);
    uint32_t h = hash_sig(xs);
    uint32_t e;
    while ((e = s_ht[h]) != 0u) {
        const int o = (int)e - 1;
        if (__ldg(&g_psig[o]) == xs && fsu_full_cmp(b, o))
            out[(size_t)b * OUT_F + o] = 1.0f;
        h = (h + 1) & (HT_SIZE - 1);
    }
}

extern "C" void kernel_launch(void* const* d_in, const int* in_sizes, int n_in,
                              void* d_out, int out_size)
{
    const float* x   = (const float*)d_in[0];
    const float* w   = (const float*)d_in[1];
    const float* rng = (const float*)d_in[2];
    float* out = (float*)d_out;

    // (BATCH + OUT_F) warps = 8192 -> 1024 blocks of 8 warps; each block also
    // zero-fills 4096 float4 of the output.
    fsu_pack_zero_kernel<<<1024, 256>>>(x, w, rng,
                                        reinterpret_cast<float4*>(out));

    fsu_match_kernel<<<BATCH / 1024, 1024>>>(out);
}